// round 9
// baseline (speedup 1.0000x reference)
#include <cuda_runtime.h>
#include <cstdint>

#define N_FEAT 512
#define N_HID  16
#define N_CLS  40
#define MAX_NODES 100000

// Scratch (allocation-free: __device__ globals)
__device__ float g_support1[MAX_NODES * N_HID];  // X @ W1
__device__ float g_agg1[MAX_NODES * N_HID];      // segment_sum conv1
__device__ float g_agg2[MAX_NODES * N_HID];      // segment_sum conv2 (16-dim)

#define FMA_F32X2(d, a, b, c) \
    asm("fma.rn.f32x2 %0, %1, %2, %3;" : "=l"(d) : "l"(a), "l"(b), "l"(c))

// ---------------------------------------------------------------------------
// Kernel 0: zero both aggregation buffers
// ---------------------------------------------------------------------------
__global__ void zero_kernel(int n_float4) {
    int i = blockIdx.x * blockDim.x + threadIdx.x;
    if (i >= n_float4) return;
    float4 z = make_float4(0.f, 0.f, 0.f, 0.f);
    reinterpret_cast<float4*>(g_agg1)[i] = z;
    reinterpret_cast<float4*>(g_agg2)[i] = z;
}

// ---------------------------------------------------------------------------
// Kernel 1: support1 = X @ W1   [nNodes,512] @ [512,16]
// 64 thr/block, 4 rows/thread (t, t+64, t+128, t+192) = 256 rows/block,
// 391 blocks. X staged coalesced via padded smem tile; W chunk in SMEM,
// its LDS.128 reads amortized over 4 rows -> crossbar/FMA ratio ~0.6.
// ---------------------------------------------------------------------------
#define GKC   16
#define GROWS 256
#define GPAD  17

__global__ __launch_bounds__(64, 8) void gemm1_kernel(
    const float* __restrict__ X, const float* __restrict__ W1, int nNodes)
{
    __shared__ float tile[GROWS * GPAD];              // 17408 B
    __shared__ __align__(16) float sWc[GKC * N_HID];  // 1 KB

    int t = threadIdx.x;
    int rowbase = blockIdx.x * GROWS;

    unsigned long long accA[8], accB[8], accC[8], accD[8];
    #pragma unroll
    for (int p = 0; p < 8; p++) {
        accA[p] = 0ULL; accB[p] = 0ULL; accC[p] = 0ULL; accD[p] = 0ULL;
    }

    for (int kc = 0; kc < N_FEAT; kc += GKC) {
        // W chunk: rows kc..kc+15 contiguous (row-major [512][16]) = 256 floats
        sWc[t]       = W1[kc * N_HID + t];
        sWc[t +  64] = W1[kc * N_HID + t +  64];
        sWc[t + 128] = W1[kc * N_HID + t + 128];
        sWc[t + 192] = W1[kc * N_HID + t + 192];

        // stage 256 rows x 16 floats: 1024 float4, 16 per thread, coalesced
        #pragma unroll
        for (int j = 0; j < 16; j++) {
            int idx = t + 64 * j;
            int row = idx >> 2;        // 0..255
            int c4  = idx & 3;         // 0..3
            int grow = rowbase + row;
            float4 v = make_float4(0.f, 0.f, 0.f, 0.f);
            if (grow < nNodes)
                v = *reinterpret_cast<const float4*>(
                        X + (size_t)grow * N_FEAT + kc + c4 * 4);
            float* tp = tile + row * GPAD + c4 * 4;
            tp[0] = v.x; tp[1] = v.y; tp[2] = v.z; tp[3] = v.w;
        }
        __syncthreads();

        const float* tA = tile + t * GPAD;
        const float* tB = tile + (t +  64) * GPAD;
        const float* tC = tile + (t + 128) * GPAD;
        const float* tD = tile + (t + 192) * GPAD;

        #pragma unroll
        for (int kk = 0; kk < GKC; kk++) {
            float xa = tA[kk];
            float xb = tB[kk];
            float xc = tC[kk];
            float xd = tD[kk];
            unsigned long long xxa, xxb, xxc, xxd;
            asm("mov.b64 %0, {%1, %1};" : "=l"(xxa) : "f"(xa));
            asm("mov.b64 %0, {%1, %1};" : "=l"(xxb) : "f"(xb));
            asm("mov.b64 %0, {%1, %1};" : "=l"(xxc) : "f"(xc));
            asm("mov.b64 %0, {%1, %1};" : "=l"(xxd) : "f"(xd));

            const ulonglong2* wr =
                reinterpret_cast<const ulonglong2*>(sWc + kk * N_HID);
            ulonglong2 w0 = wr[0];   // cols 0-3  (LDS.128 broadcast)
            ulonglong2 w1 = wr[1];   // cols 4-7
            ulonglong2 w2 = wr[2];   // cols 8-11
            ulonglong2 w3 = wr[3];   // cols 12-15

            FMA_F32X2(accA[0], xxa, w0.x, accA[0]);
            FMA_F32X2(accA[1], xxa, w0.y, accA[1]);
            FMA_F32X2(accA[2], xxa, w1.x, accA[2]);
            FMA_F32X2(accA[3], xxa, w1.y, accA[3]);
            FMA_F32X2(accA[4], xxa, w2.x, accA[4]);
            FMA_F32X2(accA[5], xxa, w2.y, accA[5]);
            FMA_F32X2(accA[6], xxa, w3.x, accA[6]);
            FMA_F32X2(accA[7], xxa, w3.y, accA[7]);

            FMA_F32X2(accB[0], xxb, w0.x, accB[0]);
            FMA_F32X2(accB[1], xxb, w0.y, accB[1]);
            FMA_F32X2(accB[2], xxb, w1.x, accB[2]);
            FMA_F32X2(accB[3], xxb, w1.y, accB[3]);
            FMA_F32X2(accB[4], xxb, w2.x, accB[4]);
            FMA_F32X2(accB[5], xxb, w2.y, accB[5]);
            FMA_F32X2(accB[6], xxb, w3.x, accB[6]);
            FMA_F32X2(accB[7], xxb, w3.y, accB[7]);

            FMA_F32X2(accC[0], xxc, w0.x, accC[0]);
            FMA_F32X2(accC[1], xxc, w0.y, accC[1]);
            FMA_F32X2(accC[2], xxc, w1.x, accC[2]);
            FMA_F32X2(accC[3], xxc, w1.y, accC[3]);
            FMA_F32X2(accC[4], xxc, w2.x, accC[4]);
            FMA_F32X2(accC[5], xxc, w2.y, accC[5]);
            FMA_F32X2(accC[6], xxc, w3.x, accC[6]);
            FMA_F32X2(accC[7], xxc, w3.y, accC[7]);

            FMA_F32X2(accD[0], xxd, w0.x, accD[0]);
            FMA_F32X2(accD[1], xxd, w0.y, accD[1]);
            FMA_F32X2(accD[2], xxd, w1.x, accD[2]);
            FMA_F32X2(accD[3], xxd, w1.y, accD[3]);
            FMA_F32X2(accD[4], xxd, w2.x, accD[4]);
            FMA_F32X2(accD[5], xxd, w2.y, accD[5]);
            FMA_F32X2(accD[6], xxd, w3.x, accD[6]);
            FMA_F32X2(accD[7], xxd, w3.y, accD[7]);
        }
        __syncthreads();
    }

    #pragma unroll
    for (int rsel = 0; rsel < 4; rsel++) {
        int r = rowbase + t + rsel * 64;
        if (r >= nNodes) continue;
        unsigned long long* acc =
            (rsel == 0) ? accA : (rsel == 1) ? accB : (rsel == 2) ? accC : accD;
        float* o = g_support1 + (size_t)r * N_HID;
        #pragma unroll
        for (int q = 0; q < 4; q++) {
            ulonglong2 st; st.x = acc[q * 2]; st.y = acc[q * 2 + 1];
            *reinterpret_cast<ulonglong2*>(o + q * 4) = st;
        }
    }
}

// ---------------------------------------------------------------------------
// Kernel 2a: conv1 aggregation (4 lanes/edge, red.global.add.v4)
// ---------------------------------------------------------------------------
__global__ __launch_bounds__(256) void aggregate1_kernel(
    const int* __restrict__ src, const int* __restrict__ dst,
    const float* __restrict__ ew, int nEdges)
{
    int gid = blockIdx.x * blockDim.x + threadIdx.x;
    int e = gid >> 2;
    if (e >= nEdges) return;
    int c = (gid & 3) << 2;

    int s = __ldg(src + e);
    int d = __ldg(dst + e);
    float w = __ldg(ew + e);

    float4 v = *reinterpret_cast<const float4*>(g_support1 + (size_t)s * N_HID + c);
    float* o = g_agg1 + (size_t)d * N_HID + c;
    asm volatile("red.global.add.v4.f32 [%0], {%1, %2, %3, %4};"
                 :: "l"(o), "f"(v.x * w), "f"(v.y * w), "f"(v.z * w), "f"(v.w * w)
                 : "memory");
}

// ---------------------------------------------------------------------------
// Kernel 2b: conv2 aggregation, fused bias+relu on the gathered value:
//   agg2[d] += w * relu(agg1[s] + b1)
// ---------------------------------------------------------------------------
__global__ __launch_bounds__(256) void aggregate2_kernel(
    const int* __restrict__ src, const int* __restrict__ dst,
    const float* __restrict__ ew, const float* __restrict__ b1, int nEdges)
{
    int gid = blockIdx.x * blockDim.x + threadIdx.x;
    int e = gid >> 2;
    if (e >= nEdges) return;
    int c = (gid & 3) << 2;

    int s = __ldg(src + e);
    int d = __ldg(dst + e);
    float w = __ldg(ew + e);

    float4 v = *reinterpret_cast<const float4*>(g_agg1 + (size_t)s * N_HID + c);
    float4 b = *reinterpret_cast<const float4*>(b1 + c);
    v.x = fmaxf(v.x + b.x, 0.f) * w;
    v.y = fmaxf(v.y + b.y, 0.f) * w;
    v.z = fmaxf(v.z + b.z, 0.f) * w;
    v.w = fmaxf(v.w + b.w, 0.f) * w;

    float* o = g_agg2 + (size_t)d * N_HID + c;
    asm volatile("red.global.add.v4.f32 [%0], {%1, %2, %3, %4};"
                 :: "l"(o), "f"(v.x), "f"(v.y), "f"(v.z), "f"(v.w)
                 : "memory");
}

// ---------------------------------------------------------------------------
// Kernel 3: out = log_softmax(agg2 @ W2 + b2)
// ---------------------------------------------------------------------------
__global__ __launch_bounds__(128) void head_kernel(
    const float* __restrict__ W2, const float* __restrict__ b2,
    float* __restrict__ out, int nNodes)
{
    __shared__ float sW[N_HID * N_CLS];
    __shared__ float sb[N_CLS];
    for (int i = threadIdx.x; i < N_HID * N_CLS; i += blockDim.x) sW[i] = W2[i];
    for (int i = threadIdx.x; i < N_CLS; i += blockDim.x) sb[i] = b2[i];
    __syncthreads();

    int node = blockIdx.x * blockDim.x + threadIdx.x;
    if (node >= nNodes) return;

    float v[N_HID];
    const float4* vp = reinterpret_cast<const float4*>(g_agg2 + (size_t)node * N_HID);
    #pragma unroll
    for (int q = 0; q < 4; q++) {
        float4 tt = vp[q];
        v[q * 4 + 0] = tt.x; v[q * 4 + 1] = tt.y; v[q * 4 + 2] = tt.z; v[q * 4 + 3] = tt.w;
    }

    float y[N_CLS];
    #pragma unroll
    for (int c = 0; c < N_CLS; c++) y[c] = sb[c];
    #pragma unroll
    for (int k = 0; k < N_HID; k++) {
        float vk = v[k];
        const float* wr = sW + k * N_CLS;
        #pragma unroll
        for (int c = 0; c < N_CLS; c++)
            y[c] = fmaf(vk, wr[c], y[c]);
    }

    float mx = y[0];
    #pragma unroll
    for (int c = 1; c < N_CLS; c++) mx = fmaxf(mx, y[c]);
    float sum = 0.f;
    #pragma unroll
    for (int c = 0; c < N_CLS; c++) sum += __expf(y[c] - mx);
    float lse = mx + __logf(sum);

    float* o = out + (size_t)node * N_CLS;
    #pragma unroll
    for (int q = 0; q < N_CLS / 4; q++) {
        float4 st = make_float4(y[q * 4 + 0] - lse, y[q * 4 + 1] - lse,
                                y[q * 4 + 2] - lse, y[q * 4 + 3] - lse);
        *reinterpret_cast<float4*>(o + q * 4) = st;
    }
}

// ---------------------------------------------------------------------------
// Launcher — zero forked onto a side stream, overlapping gemm1.
// ---------------------------------------------------------------------------
extern "C" void kernel_launch(void* const* d_in, const int* in_sizes, int n_in,
                              void* d_out, int out_size)
{
    const float* x        = (const float*)d_in[0];
    const int*   edge_src = (const int*)  d_in[1];
    const int*   edge_dst = (const int*)  d_in[2];
    const float* edge_w   = (const float*)d_in[3];
    const float* W1       = (const float*)d_in[4];
    const float* b1       = (const float*)d_in[5];
    const float* W2       = (const float*)d_in[6];
    const float* b2       = (const float*)d_in[7];
    float* out = (float*)d_out;

    int nNodes = in_sizes[0] / N_FEAT;
    int nEdges = in_sizes[1];
    int n_f4 = nNodes * N_HID / 4;

    cudaStream_t s2 = 0;
    cudaEvent_t evF = 0, evJ = 0;
    bool forked =
        (cudaStreamCreateWithFlags(&s2, cudaStreamNonBlocking) == cudaSuccess) &&
        (cudaEventCreateWithFlags(&evF, cudaEventDisableTiming) == cudaSuccess) &&
        (cudaEventCreateWithFlags(&evJ, cudaEventDisableTiming) == cudaSuccess);
    if (!forked) s2 = 0;

    if (forked) {
        cudaEventRecord(evF, 0);
        cudaStreamWaitEvent(s2, evF, 0);
    }

    zero_kernel<<<(n_f4 + 255) / 256, 256, 0, s2>>>(n_f4);

    gemm1_kernel<<<(nNodes + GROWS - 1) / GROWS, 64>>>(x, W1, nNodes);

    if (forked) {
        cudaEventRecord(evJ, s2);
        cudaStreamWaitEvent(0, evJ, 0);
    }

    int aggThreads = nEdges * 4;
    aggregate1_kernel<<<(aggThreads + 255) / 256, 256>>>(
        edge_src, edge_dst, edge_w, nEdges);

    aggregate2_kernel<<<(aggThreads + 255) / 256, 256>>>(
        edge_src, edge_dst, edge_w, b1, nEdges);

    head_kernel<<<(nNodes + 127) / 128, 128>>>(W2, b2, out, nNodes);
}

// round 10
// speedup vs baseline: 1.1573x; 1.1573x over previous
#include <cuda_runtime.h>
#include <cstdint>

#define N_FEAT 512
#define N_HID  16
#define N_CLS  40
#define MAX_NODES 100000

// Scratch (allocation-free: __device__ globals)
__device__ float g_support1[MAX_NODES * N_HID];  // X @ W1
__device__ float g_agg1[MAX_NODES * N_HID];      // segment_sum conv1
__device__ float g_agg2[MAX_NODES * N_HID];      // segment_sum conv2 (16-dim)

#define FMA_F32X2(d, a, b, c) \
    asm("fma.rn.f32x2 %0, %1, %2, %3;" : "=l"(d) : "l"(a), "l"(b), "l"(c))

// ---------------------------------------------------------------------------
// Kernel 0: zero both aggregation buffers
// ---------------------------------------------------------------------------
__global__ void zero_kernel(int n_float4) {
    int i = blockIdx.x * blockDim.x + threadIdx.x;
    if (i >= n_float4) return;
    float4 z = make_float4(0.f, 0.f, 0.f, 0.f);
    reinterpret_cast<float4*>(g_agg1)[i] = z;
    reinterpret_cast<float4*>(g_agg2)[i] = z;
}

// ---------------------------------------------------------------------------
// Kernel 1: support1 = X @ W1   [nNodes,512] @ [512,16]
// 128 thr/block, 2 rows/thread = 256 rows/block (391 blocks).
// Software-pipelined: chunk k+1 prefetched into registers while chunk k
// computes -> LDGs in flight through the compute phase (DRAM duty ~100%).
// ---------------------------------------------------------------------------
#define GKC   16
#define GROWS 256
#define GPAD  17

__global__ __launch_bounds__(128) void gemm1_kernel(
    const float* __restrict__ X, const float* __restrict__ W1, int nNodes)
{
    __shared__ float tile[GROWS * GPAD];              // 17408 B
    __shared__ __align__(16) float sWc[GKC * N_HID];  // 1 KB

    int t = threadIdx.x;
    int rowbase = blockIdx.x * GROWS;

    // per-thread staging coordinates (constant across chunks)
    int srow[8], sc4[8];
    const float4* sptr[8];
    #pragma unroll
    for (int j = 0; j < 8; j++) {
        int idx = t + 128 * j;
        srow[j] = idx >> 2;          // 0..255
        sc4[j]  = idx & 3;           // 0..3
        int grow = rowbase + srow[j];
        sptr[j] = (grow < nNodes)
            ? reinterpret_cast<const float4*>(X + (size_t)grow * N_FEAT + sc4[j] * 4)
            : nullptr;
    }

    unsigned long long accA[8], accB[8];
    #pragma unroll
    for (int p = 0; p < 8; p++) { accA[p] = 0ULL; accB[p] = 0ULL; }

    // prefetch chunk 0
    float4 pf[8];
    #pragma unroll
    for (int j = 0; j < 8; j++)
        pf[j] = sptr[j] ? sptr[j][0] : make_float4(0.f, 0.f, 0.f, 0.f);
    float wpf0 = W1[t];
    float wpf1 = W1[t + 128];

    for (int kc = 0; kc < N_FEAT; kc += GKC) {
        // store prefetched chunk into smem
        #pragma unroll
        for (int j = 0; j < 8; j++) {
            float* tp = tile + srow[j] * GPAD + sc4[j] * 4;
            tp[0] = pf[j].x; tp[1] = pf[j].y; tp[2] = pf[j].z; tp[3] = pf[j].w;
        }
        sWc[t]       = wpf0;
        sWc[t + 128] = wpf1;
        __syncthreads();

        // prefetch NEXT chunk (LDGs overlap the compute below)
        int kn = kc + GKC;
        if (kn < N_FEAT) {
            #pragma unroll
            for (int j = 0; j < 8; j++)
                pf[j] = sptr[j] ? sptr[j][kn >> 2]
                                : make_float4(0.f, 0.f, 0.f, 0.f);
            wpf0 = W1[kn * N_HID + t];
            wpf1 = W1[kn * N_HID + t + 128];
        }

        const float* tA = tile + t * GPAD;
        const float* tB = tile + (t + 128) * GPAD;

        #pragma unroll
        for (int kk = 0; kk < GKC; kk++) {
            float xa = tA[kk];
            float xb = tB[kk];
            unsigned long long xxa, xxb;
            asm("mov.b64 %0, {%1, %1};" : "=l"(xxa) : "f"(xa));
            asm("mov.b64 %0, {%1, %1};" : "=l"(xxb) : "f"(xb));

            const ulonglong2* wr =
                reinterpret_cast<const ulonglong2*>(sWc + kk * N_HID);
            ulonglong2 w0 = wr[0];   // broadcast LDS.128
            ulonglong2 w1 = wr[1];
            ulonglong2 w2 = wr[2];
            ulonglong2 w3 = wr[3];

            FMA_F32X2(accA[0], xxa, w0.x, accA[0]);
            FMA_F32X2(accA[1], xxa, w0.y, accA[1]);
            FMA_F32X2(accA[2], xxa, w1.x, accA[2]);
            FMA_F32X2(accA[3], xxa, w1.y, accA[3]);
            FMA_F32X2(accA[4], xxa, w2.x, accA[4]);
            FMA_F32X2(accA[5], xxa, w2.y, accA[5]);
            FMA_F32X2(accA[6], xxa, w3.x, accA[6]);
            FMA_F32X2(accA[7], xxa, w3.y, accA[7]);

            FMA_F32X2(accB[0], xxb, w0.x, accB[0]);
            FMA_F32X2(accB[1], xxb, w0.y, accB[1]);
            FMA_F32X2(accB[2], xxb, w1.x, accB[2]);
            FMA_F32X2(accB[3], xxb, w1.y, accB[3]);
            FMA_F32X2(accB[4], xxb, w2.x, accB[4]);
            FMA_F32X2(accB[5], xxb, w2.y, accB[5]);
            FMA_F32X2(accB[6], xxb, w3.x, accB[6]);
            FMA_F32X2(accB[7], xxb, w3.y, accB[7]);
        }
        __syncthreads();
    }

    int r0 = rowbase + t;
    int r1 = rowbase + t + 128;
    if (r0 < nNodes) {
        float* o = g_support1 + (size_t)r0 * N_HID;
        #pragma unroll
        for (int q = 0; q < 4; q++) {
            ulonglong2 st; st.x = accA[q * 2]; st.y = accA[q * 2 + 1];
            *reinterpret_cast<ulonglong2*>(o + q * 4) = st;
        }
    }
    if (r1 < nNodes) {
        float* o = g_support1 + (size_t)r1 * N_HID;
        #pragma unroll
        for (int q = 0; q < 4; q++) {
            ulonglong2 st; st.x = accB[q * 2]; st.y = accB[q * 2 + 1];
            *reinterpret_cast<ulonglong2*>(o + q * 4) = st;
        }
    }
}

// ---------------------------------------------------------------------------
// Kernel 2a: conv1 aggregation (4 lanes/edge, red.global.add.v4)
// ---------------------------------------------------------------------------
__global__ __launch_bounds__(256) void aggregate1_kernel(
    const int* __restrict__ src, const int* __restrict__ dst,
    const float* __restrict__ ew, int nEdges)
{
    int gid = blockIdx.x * blockDim.x + threadIdx.x;
    int e = gid >> 2;
    if (e >= nEdges) return;
    int c = (gid & 3) << 2;

    int s = __ldg(src + e);
    int d = __ldg(dst + e);
    float w = __ldg(ew + e);

    float4 v = *reinterpret_cast<const float4*>(g_support1 + (size_t)s * N_HID + c);
    float* o = g_agg1 + (size_t)d * N_HID + c;
    asm volatile("red.global.add.v4.f32 [%0], {%1, %2, %3, %4};"
                 :: "l"(o), "f"(v.x * w), "f"(v.y * w), "f"(v.z * w), "f"(v.w * w)
                 : "memory");
}

// ---------------------------------------------------------------------------
// Kernel 2b: conv2 aggregation, fused bias+relu on the gathered value:
//   agg2[d] += w * relu(agg1[s] + b1)
// ---------------------------------------------------------------------------
__global__ __launch_bounds__(256) void aggregate2_kernel(
    const int* __restrict__ src, const int* __restrict__ dst,
    const float* __restrict__ ew, const float* __restrict__ b1, int nEdges)
{
    int gid = blockIdx.x * blockDim.x + threadIdx.x;
    int e = gid >> 2;
    if (e >= nEdges) return;
    int c = (gid & 3) << 2;

    int s = __ldg(src + e);
    int d = __ldg(dst + e);
    float w = __ldg(ew + e);

    float4 v = *reinterpret_cast<const float4*>(g_agg1 + (size_t)s * N_HID + c);
    float4 b = *reinterpret_cast<const float4*>(b1 + c);
    v.x = fmaxf(v.x + b.x, 0.f) * w;
    v.y = fmaxf(v.y + b.y, 0.f) * w;
    v.z = fmaxf(v.z + b.z, 0.f) * w;
    v.w = fmaxf(v.w + b.w, 0.f) * w;

    float* o = g_agg2 + (size_t)d * N_HID + c;
    asm volatile("red.global.add.v4.f32 [%0], {%1, %2, %3, %4};"
                 :: "l"(o), "f"(v.x), "f"(v.y), "f"(v.z), "f"(v.w)
                 : "memory");
}

// ---------------------------------------------------------------------------
// Kernel 3: out = log_softmax(agg2 @ W2 + b2)
// ---------------------------------------------------------------------------
__global__ __launch_bounds__(128) void head_kernel(
    const float* __restrict__ W2, const float* __restrict__ b2,
    float* __restrict__ out, int nNodes)
{
    __shared__ float sW[N_HID * N_CLS];
    __shared__ float sb[N_CLS];
    for (int i = threadIdx.x; i < N_HID * N_CLS; i += blockDim.x) sW[i] = W2[i];
    for (int i = threadIdx.x; i < N_CLS; i += blockDim.x) sb[i] = b2[i];
    __syncthreads();

    int node = blockIdx.x * blockDim.x + threadIdx.x;
    if (node >= nNodes) return;

    float v[N_HID];
    const float4* vp = reinterpret_cast<const float4*>(g_agg2 + (size_t)node * N_HID);
    #pragma unroll
    for (int q = 0; q < 4; q++) {
        float4 tt = vp[q];
        v[q * 4 + 0] = tt.x; v[q * 4 + 1] = tt.y; v[q * 4 + 2] = tt.z; v[q * 4 + 3] = tt.w;
    }

    float y[N_CLS];
    #pragma unroll
    for (int c = 0; c < N_CLS; c++) y[c] = sb[c];
    #pragma unroll
    for (int k = 0; k < N_HID; k++) {
        float vk = v[k];
        const float* wr = sW + k * N_CLS;
        #pragma unroll
        for (int c = 0; c < N_CLS; c++)
            y[c] = fmaf(vk, wr[c], y[c]);
    }

    float mx = y[0];
    #pragma unroll
    for (int c = 1; c < N_CLS; c++) mx = fmaxf(mx, y[c]);
    float sum = 0.f;
    #pragma unroll
    for (int c = 0; c < N_CLS; c++) sum += __expf(y[c] - mx);
    float lse = mx + __logf(sum);

    float* o = out + (size_t)node * N_CLS;
    #pragma unroll
    for (int q = 0; q < N_CLS / 4; q++) {
        float4 st = make_float4(y[q * 4 + 0] - lse, y[q * 4 + 1] - lse,
                                y[q * 4 + 2] - lse, y[q * 4 + 3] - lse);
        *reinterpret_cast<float4*>(o + q * 4) = st;
    }
}

// ---------------------------------------------------------------------------
// Launcher — zero forked onto a side stream, overlapping gemm1.
// ---------------------------------------------------------------------------
extern "C" void kernel_launch(void* const* d_in, const int* in_sizes, int n_in,
                              void* d_out, int out_size)
{
    const float* x        = (const float*)d_in[0];
    const int*   edge_src = (const int*)  d_in[1];
    const int*   edge_dst = (const int*)  d_in[2];
    const float* edge_w   = (const float*)d_in[3];
    const float* W1       = (const float*)d_in[4];
    const float* b1       = (const float*)d_in[5];
    const float* W2       = (const float*)d_in[6];
    const float* b2       = (const float*)d_in[7];
    float* out = (float*)d_out;

    int nNodes = in_sizes[0] / N_FEAT;
    int nEdges = in_sizes[1];
    int n_f4 = nNodes * N_HID / 4;

    cudaStream_t s2 = 0;
    cudaEvent_t evF = 0, evJ = 0;
    bool forked =
        (cudaStreamCreateWithFlags(&s2, cudaStreamNonBlocking) == cudaSuccess) &&
        (cudaEventCreateWithFlags(&evF, cudaEventDisableTiming) == cudaSuccess) &&
        (cudaEventCreateWithFlags(&evJ, cudaEventDisableTiming) == cudaSuccess);
    if (!forked) s2 = 0;

    if (forked) {
        cudaEventRecord(evF, 0);
        cudaStreamWaitEvent(s2, evF, 0);
    }

    zero_kernel<<<(n_f4 + 255) / 256, 256, 0, s2>>>(n_f4);

    gemm1_kernel<<<(nNodes + GROWS - 1) / GROWS, 128>>>(x, W1, nNodes);

    if (forked) {
        cudaEventRecord(evJ, s2);
        cudaStreamWaitEvent(0, evJ, 0);
    }

    int aggThreads = nEdges * 4;
    aggregate1_kernel<<<(aggThreads + 255) / 256, 256>>>(
        edge_src, edge_dst, edge_w, nEdges);

    aggregate2_kernel<<<(aggThreads + 255) / 256, 256>>>(
        edge_src, edge_dst, edge_w, b1, nEdges);

    head_kernel<<<(nNodes + 127) / 128, 128>>>(W2, b2, out, nNodes);
}

// round 11
// speedup vs baseline: 1.2015x; 1.0382x over previous
#include <cuda_runtime.h>
#include <cstdint>

#define N_FEAT 512
#define N_HID  16
#define N_CLS  40
#define MAX_NODES 100000

// Scratch (allocation-free: __device__ globals)
__device__ float g_support1[MAX_NODES * N_HID];  // X @ W1
__device__ float g_agg1[MAX_NODES * N_HID];      // segment_sum conv1
__device__ float g_agg2[MAX_NODES * N_HID];      // segment_sum conv2 (16-dim)

#define FMA_F32X2(d, a, b, c) \
    asm("fma.rn.f32x2 %0, %1, %2, %3;" : "=l"(d) : "l"(a), "l"(b), "l"(c))

#define CP_ASYNC8(dst, src, srcsz) \
    asm volatile("cp.async.ca.shared.global [%0], [%1], 8, %2;" \
                 :: "r"(dst), "l"(src), "r"(srcsz))
#define CP_COMMIT() asm volatile("cp.async.commit_group;" ::: "memory")
#define CP_WAIT1()  asm volatile("cp.async.wait_group 1;" ::: "memory")
#define CP_WAIT0()  asm volatile("cp.async.wait_group 0;" ::: "memory")

__device__ __forceinline__ uint32_t smem_u32(const void* p) {
    uint32_t a;
    asm("{ .reg .u64 tmp; cvta.to.shared.u64 tmp, %1; cvt.u32.u64 %0, tmp; }"
        : "=r"(a) : "l"(p));
    return a;
}

// ---------------------------------------------------------------------------
// Kernel 0: zero both aggregation buffers
// ---------------------------------------------------------------------------
__global__ void zero_kernel(int n_float4) {
    int i = blockIdx.x * blockDim.x + threadIdx.x;
    if (i >= n_float4) return;
    float4 z = make_float4(0.f, 0.f, 0.f, 0.f);
    reinterpret_cast<float4*>(g_agg1)[i] = z;
    reinterpret_cast<float4*>(g_agg2)[i] = z;
}

// ---------------------------------------------------------------------------
// Kernel 1: support1 = X @ W1   [nNodes,512] @ [512,16]
// 128 thr/block, 2 rows/thread = 256 rows/block (391 blocks).
// cp.async (LDGSTS) double-buffered staging: chunk k+1 streams into smem
// buffer B while chunk k computes from A. No reg round-trip, depth-2 queue,
// low reg count -> DRAM duty ~100%.
// ---------------------------------------------------------------------------
#define GKC    16
#define GROWS  256
#define GSTR   18            // tile row stride in floats (72 B, 8B-aligned)
#define NCHUNK (N_FEAT / GKC)

__global__ __launch_bounds__(128) void gemm1_kernel(
    const float* __restrict__ X, const float* __restrict__ W1, int nNodes)
{
    __shared__ __align__(16) float tile[2][GROWS * GSTR];   // 2 x 18432 B
    __shared__ __align__(16) float sWc[2][GKC * N_HID];     // 2 x 1024 B

    int t = threadIdx.x;
    int rowbase = blockIdx.x * GROWS;

    uint32_t tile_b = smem_u32(&tile[0][0]);
    uint32_t wc_b   = smem_u32(&sWc[0][0]);

    // staging coords: 16 x 8-byte copies per thread per chunk
    // idx = t + 128*j ; row = idx>>3 (8 x 8B per 16-float row); c8 = idx&7
    const float* srcp[16];
    uint32_t     doff[16];
    int          ssz[16];
    #pragma unroll
    for (int j = 0; j < 16; j++) {
        int idx = t + 128 * j;
        int row = idx >> 3;
        int c8  = idx & 7;
        int grow = rowbase + row;
        bool ok = (grow < nNodes);
        srcp[j] = X + (size_t)(ok ? grow : 0) * N_FEAT + c8 * 2;
        doff[j] = (uint32_t)(row * GSTR + c8 * 2) * 4u;
        ssz[j]  = ok ? 8 : 0;
    }

    unsigned long long accA[8], accB[8];
    #pragma unroll
    for (int p = 0; p < 8; p++) { accA[p] = 0ULL; accB[p] = 0ULL; }

    // issue chunk `kc` into buffer `buf`
    auto issue = [&](int kc, int buf) {
        uint32_t tb = tile_b + buf * (GROWS * GSTR * 4);
        #pragma unroll
        for (int j = 0; j < 16; j++)
            CP_ASYNC8(tb + doff[j], srcp[j] + kc, ssz[j]);
        // W chunk: 256 floats = 128 x 8B, one per thread
        CP_ASYNC8(wc_b + buf * (GKC * N_HID * 4) + t * 8,
                  W1 + kc * N_HID + t * 2, 8);
    };

    issue(0, 0);
    CP_COMMIT();

    for (int c = 0; c < NCHUNK; c++) {
        int cur = c & 1;
        if (c < NCHUNK - 1) {
            issue((c + 1) * GKC, 1 - cur);
            CP_COMMIT();
            CP_WAIT1();          // chunk c landed; c+1 still in flight
        } else {
            CP_WAIT0();
        }
        __syncthreads();

        const float* tA = &tile[cur][t * GSTR];
        const float* tB = &tile[cur][(t + 128) * GSTR];
        const float* wc = &sWc[cur][0];

        #pragma unroll
        for (int kk = 0; kk < GKC; kk++) {
            float xa = tA[kk];
            float xb = tB[kk];
            unsigned long long xxa, xxb;
            asm("mov.b64 %0, {%1, %1};" : "=l"(xxa) : "f"(xa));
            asm("mov.b64 %0, {%1, %1};" : "=l"(xxb) : "f"(xb));

            const ulonglong2* wr =
                reinterpret_cast<const ulonglong2*>(wc + kk * N_HID);
            ulonglong2 w0 = wr[0];
            ulonglong2 w1 = wr[1];
            ulonglong2 w2 = wr[2];
            ulonglong2 w3 = wr[3];

            FMA_F32X2(accA[0], xxa, w0.x, accA[0]);
            FMA_F32X2(accA[1], xxa, w0.y, accA[1]);
            FMA_F32X2(accA[2], xxa, w1.x, accA[2]);
            FMA_F32X2(accA[3], xxa, w1.y, accA[3]);
            FMA_F32X2(accA[4], xxa, w2.x, accA[4]);
            FMA_F32X2(accA[5], xxa, w2.y, accA[5]);
            FMA_F32X2(accA[6], xxa, w3.x, accA[6]);
            FMA_F32X2(accA[7], xxa, w3.y, accA[7]);

            FMA_F32X2(accB[0], xxb, w0.x, accB[0]);
            FMA_F32X2(accB[1], xxb, w0.y, accB[1]);
            FMA_F32X2(accB[2], xxb, w1.x, accB[2]);
            FMA_F32X2(accB[3], xxb, w1.y, accB[3]);
            FMA_F32X2(accB[4], xxb, w2.x, accB[4]);
            FMA_F32X2(accB[5], xxb, w2.y, accB[5]);
            FMA_F32X2(accB[6], xxb, w3.x, accB[6]);
            FMA_F32X2(accB[7], xxb, w3.y, accB[7]);
        }
        __syncthreads();
    }

    int r0 = rowbase + t;
    int r1 = rowbase + t + 128;
    if (r0 < nNodes) {
        float* o = g_support1 + (size_t)r0 * N_HID;
        #pragma unroll
        for (int q = 0; q < 4; q++) {
            ulonglong2 st; st.x = accA[q * 2]; st.y = accA[q * 2 + 1];
            *reinterpret_cast<ulonglong2*>(o + q * 4) = st;
        }
    }
    if (r1 < nNodes) {
        float* o = g_support1 + (size_t)r1 * N_HID;
        #pragma unroll
        for (int q = 0; q < 4; q++) {
            ulonglong2 st; st.x = accB[q * 2]; st.y = accB[q * 2 + 1];
            *reinterpret_cast<ulonglong2*>(o + q * 4) = st;
        }
    }
}

// ---------------------------------------------------------------------------
// Kernel 2a: conv1 aggregation (4 lanes/edge, red.global.add.v4)
// ---------------------------------------------------------------------------
__global__ __launch_bounds__(256) void aggregate1_kernel(
    const int* __restrict__ src, const int* __restrict__ dst,
    const float* __restrict__ ew, int nEdges)
{
    int gid = blockIdx.x * blockDim.x + threadIdx.x;
    int e = gid >> 2;
    if (e >= nEdges) return;
    int c = (gid & 3) << 2;

    int s = __ldg(src + e);
    int d = __ldg(dst + e);
    float w = __ldg(ew + e);

    float4 v = *reinterpret_cast<const float4*>(g_support1 + (size_t)s * N_HID + c);
    float* o = g_agg1 + (size_t)d * N_HID + c;
    asm volatile("red.global.add.v4.f32 [%0], {%1, %2, %3, %4};"
                 :: "l"(o), "f"(v.x * w), "f"(v.y * w), "f"(v.z * w), "f"(v.w * w)
                 : "memory");
}

// ---------------------------------------------------------------------------
// Kernel 2b: conv2 aggregation, fused bias+relu on the gathered value:
//   agg2[d] += w * relu(agg1[s] + b1)
// ---------------------------------------------------------------------------
__global__ __launch_bounds__(256) void aggregate2_kernel(
    const int* __restrict__ src, const int* __restrict__ dst,
    const float* __restrict__ ew, const float* __restrict__ b1, int nEdges)
{
    int gid = blockIdx.x * blockDim.x + threadIdx.x;
    int e = gid >> 2;
    if (e >= nEdges) return;
    int c = (gid & 3) << 2;

    int s = __ldg(src + e);
    int d = __ldg(dst + e);
    float w = __ldg(ew + e);

    float4 v = *reinterpret_cast<const float4*>(g_agg1 + (size_t)s * N_HID + c);
    float4 b = *reinterpret_cast<const float4*>(b1 + c);
    v.x = fmaxf(v.x + b.x, 0.f) * w;
    v.y = fmaxf(v.y + b.y, 0.f) * w;
    v.z = fmaxf(v.z + b.z, 0.f) * w;
    v.w = fmaxf(v.w + b.w, 0.f) * w;

    float* o = g_agg2 + (size_t)d * N_HID + c;
    asm volatile("red.global.add.v4.f32 [%0], {%1, %2, %3, %4};"
                 :: "l"(o), "f"(v.x), "f"(v.y), "f"(v.z), "f"(v.w)
                 : "memory");
}

// ---------------------------------------------------------------------------
// Kernel 3: out = log_softmax(agg2 @ W2 + b2)
// ---------------------------------------------------------------------------
__global__ __launch_bounds__(128) void head_kernel(
    const float* __restrict__ W2, const float* __restrict__ b2,
    float* __restrict__ out, int nNodes)
{
    __shared__ float sW[N_HID * N_CLS];
    __shared__ float sb[N_CLS];
    for (int i = threadIdx.x; i < N_HID * N_CLS; i += blockDim.x) sW[i] = W2[i];
    for (int i = threadIdx.x; i < N_CLS; i += blockDim.x) sb[i] = b2[i];
    __syncthreads();

    int node = blockIdx.x * blockDim.x + threadIdx.x;
    if (node >= nNodes) return;

    float v[N_HID];
    const float4* vp = reinterpret_cast<const float4*>(g_agg2 + (size_t)node * N_HID);
    #pragma unroll
    for (int q = 0; q < 4; q++) {
        float4 tt = vp[q];
        v[q * 4 + 0] = tt.x; v[q * 4 + 1] = tt.y; v[q * 4 + 2] = tt.z; v[q * 4 + 3] = tt.w;
    }

    float y[N_CLS];
    #pragma unroll
    for (int c = 0; c < N_CLS; c++) y[c] = sb[c];
    #pragma unroll
    for (int k = 0; k < N_HID; k++) {
        float vk = v[k];
        const float* wr = sW + k * N_CLS;
        #pragma unroll
        for (int c = 0; c < N_CLS; c++)
            y[c] = fmaf(vk, wr[c], y[c]);
    }

    float mx = y[0];
    #pragma unroll
    for (int c = 1; c < N_CLS; c++) mx = fmaxf(mx, y[c]);
    float sum = 0.f;
    #pragma unroll
    for (int c = 0; c < N_CLS; c++) sum += __expf(y[c] - mx);
    float lse = mx + __logf(sum);

    float* o = out + (size_t)node * N_CLS;
    #pragma unroll
    for (int q = 0; q < N_CLS / 4; q++) {
        float4 st = make_float4(y[q * 4 + 0] - lse, y[q * 4 + 1] - lse,
                                y[q * 4 + 2] - lse, y[q * 4 + 3] - lse);
        *reinterpret_cast<float4*>(o + q * 4) = st;
    }
}

// ---------------------------------------------------------------------------
// Launcher — zero forked onto a side stream, overlapping gemm1.
// ---------------------------------------------------------------------------
extern "C" void kernel_launch(void* const* d_in, const int* in_sizes, int n_in,
                              void* d_out, int out_size)
{
    const float* x        = (const float*)d_in[0];
    const int*   edge_src = (const int*)  d_in[1];
    const int*   edge_dst = (const int*)  d_in[2];
    const float* edge_w   = (const float*)d_in[3];
    const float* W1       = (const float*)d_in[4];
    const float* b1       = (const float*)d_in[5];
    const float* W2       = (const float*)d_in[6];
    const float* b2       = (const float*)d_in[7];
    float* out = (float*)d_out;

    int nNodes = in_sizes[0] / N_FEAT;
    int nEdges = in_sizes[1];
    int n_f4 = nNodes * N_HID / 4;

    cudaStream_t s2 = 0;
    cudaEvent_t evF = 0, evJ = 0;
    bool forked =
        (cudaStreamCreateWithFlags(&s2, cudaStreamNonBlocking) == cudaSuccess) &&
        (cudaEventCreateWithFlags(&evF, cudaEventDisableTiming) == cudaSuccess) &&
        (cudaEventCreateWithFlags(&evJ, cudaEventDisableTiming) == cudaSuccess);
    if (!forked) s2 = 0;

    if (forked) {
        cudaEventRecord(evF, 0);
        cudaStreamWaitEvent(s2, evF, 0);
    }

    zero_kernel<<<(n_f4 + 255) / 256, 256, 0, s2>>>(n_f4);

    gemm1_kernel<<<(nNodes + GROWS - 1) / GROWS, 128>>>(x, W1, nNodes);

    if (forked) {
        cudaEventRecord(evJ, s2);
        cudaStreamWaitEvent(0, evJ, 0);
    }

    int aggThreads = nEdges * 4;
    aggregate1_kernel<<<(aggThreads + 255) / 256, 256>>>(
        edge_src, edge_dst, edge_w, nEdges);

    aggregate2_kernel<<<(aggThreads + 255) / 256, 256>>>(
        edge_src, edge_dst, edge_w, b1, nEdges);

    head_kernel<<<(nNodes + 127) / 128, 128>>>(W2, b2, out, nNodes);
}